// round 14
// baseline (speedup 1.0000x reference)
#include <cuda_runtime.h>
#include <cuda_fp16.h>
#include <math.h>
#include <stdint.h>

// Shapes (fixed)
#define BB 128
#define SS 1024
#define DD 256
#define AA 256
#define OO 256
#define NROWS (BB*SS)

#define TILE_R 64
#define LDA 264            // xs row stride in halfs (528B) -> conflict-free
#define LDK 40             // weight row stride in halfs (80B) -> conflict-free
#define CHUNK_B (256*LDK*2)   // 20480 bytes per 32-k weight chunk
#define NSTAGE 3

// smem byte offsets (WB region expanded to 65536 to hold fp32 x tile in tail)
#define O_XS   0               // 64*264*2 = 33792
#define O_WB   33792           // max(3*20480, 65536) = 65536
#define O_BS   99328           // 256 f32
#define O_US   100352          // 256 f32
#define O_MS   101376          // 64 f32
#define O_RED  101632          // 64*4 f32
#define O_VUS  102656          // 64 f32
#define O_MTW  102912          // 2 f32 (+pad)
#define O_QS   102928          // 64 f32
#define O_P4   103184          // 4*64 float4 = 4096
#define SMEM_BYTES 107280      // 2 CTAs = 214560 < 228KB -> occ 2

// Scratch
__device__ float g_vu[NROWS];
__device__ float g_part[NROWS/TILE_R * OO];   // per-tile output partials
__device__ float g_mt[NROWS/TILE_R];          // per-tile local max
__device__ __half g_Wh[DD * AA];    // W  transposed to [a][d], fp16
__device__ __half g_Uh[AA * OO];    // Uo transposed to [o][a], fp16

// ---------------------------------------------------------------------------
__device__ __forceinline__ uint32_t smem_u32(const void* p) {
    uint32_t a;
    asm("{ .reg .u64 t; cvta.to.shared.u64 t, %1; cvt.u32.u64 %0, t; }" : "=r"(a) : "l"(p));
    return a;
}
__device__ __forceinline__ void cp16(uint32_t dst, const void* src) {
    asm volatile("cp.async.cg.shared.global [%0], [%1], 16;" :: "r"(dst), "l"(src));
}
#define CP_COMMIT() asm volatile("cp.async.commit_group;" ::: "memory")
#define CP_WAIT0()  asm volatile("cp.async.wait_group 0;" ::: "memory")
#define CP_WAIT1()  asm volatile("cp.async.wait_group 1;" ::: "memory")

__device__ __forceinline__ void mma16(float* c, const uint32_t* a, uint32_t b0, uint32_t b1) {
    asm("mma.sync.aligned.m16n8k16.row.col.f32.f16.f16.f32 "
        "{%0,%1,%2,%3}, {%4,%5,%6,%7}, {%8,%9}, {%0,%1,%2,%3};"
        : "+f"(c[0]), "+f"(c[1]), "+f"(c[2]), "+f"(c[3])
        : "r"(a[0]), "r"(a[1]), "r"(a[2]), "r"(a[3]), "r"(b0), "r"(b1));
}
__device__ __forceinline__ void ldm4(uint32_t* d, uint32_t addr) {
    asm volatile("ldmatrix.sync.aligned.m8n8.x4.shared.b16 {%0,%1,%2,%3}, [%4];"
        : "=r"(d[0]), "=r"(d[1]), "=r"(d[2]), "=r"(d[3]) : "r"(addr));
}
__device__ __forceinline__ float tanh_fast(float a) {
    float v;
    asm("tanh.approx.f32 %0, %1;" : "=f"(v) : "f"(a));
    return v;
}

// issue one 32k x 256n fp16 chunk: 256 threads, 4 cp16 each
__device__ __forceinline__ void issue_chunk(uint32_t dst, const __half* gsrc, int tid) {
    const __half* s = gsrc + tid * 256;
    uint32_t d = dst + (uint32_t)(tid * LDK * 2);
    #pragma unroll
    for (int p = 0; p < 4; p++) cp16(d + p * 16, s + p * 8);
    CP_COMMIT();
}

// one 32-k chunk of MMAs (two 16-k steps), ldmatrix fragment loads
__device__ __forceinline__ void compute_chunk(float acc[2][8][4],
        uint32_t xs_u32, uint32_t wb_cur, int kbase,
        uint32_t a_off0, uint32_t a_off1, uint32_t b_off)
{
    #pragma unroll
    for (int ks = 0; ks < 2; ks++) {
        const uint32_t kb2 = (uint32_t)(kbase + ks * 16) * 2u;
        uint32_t a0[4], a1[4];
        ldm4(a0, xs_u32 + a_off0 * 2u + kb2);
        ldm4(a1, xs_u32 + a_off1 * 2u + kb2);
        #pragma unroll
        for (int p = 0; p < 4; p++) {
            uint32_t b[4];
            ldm4(b, wb_cur + (b_off + (uint32_t)(p * 16 * LDK)) * 2u + (uint32_t)(ks * 32));
            mma16(acc[0][2*p],   a0, b[0], b[1]);
            mma16(acc[1][2*p],   a1, b[0], b[1]);
            mma16(acc[0][2*p+1], a0, b[2], b[3]);
            mma16(acc[1][2*p+1], a1, b[2], b[3]);
        }
    }
}

// 8 chunks, 3-stage ring, ONE sync per chunk. Chunks 0,1 pre-issued into bufs 0,1.
__device__ __forceinline__ void gemm_loop(float acc[2][8][4], const __half* __restrict__ gW,
        uint32_t xs_u32, uint32_t wb_u32,
        uint32_t a_off0, uint32_t a_off1, uint32_t b_off, int tid)
{
    for (int kc = 0; kc < 8; kc++) {
        if (kc < 7) CP_WAIT1(); else CP_WAIT0();
        __syncthreads();                       // chunk kc visible; buf (kc+2)%3 free
        if (kc + 2 < 8)
            issue_chunk(wb_u32 + (uint32_t)((kc + 2) % NSTAGE) * CHUNK_B,
                        gW + (kc + 2) * 32, tid);
        compute_chunk(acc, xs_u32, wb_u32 + (uint32_t)(kc % NSTAGE) * CHUNK_B,
                      kc * 32, a_off0, a_off1, b_off);
    }
}

// ---------------------------------------------------------------------------
// Transpose + fp16 convert: g_Wh[a][d] = W[d][a], g_Uh[o][a] = Uo[a][o]
// ---------------------------------------------------------------------------
__global__ void k_prep(const float* __restrict__ W, const float* __restrict__ Uo)
{
    __shared__ float t[32][33];
    const float* src = blockIdx.z ? Uo : W;
    __half* dst = blockIdx.z ? g_Uh : g_Wh;
    int x0 = blockIdx.x * 32, y0 = blockIdx.y * 32;
    #pragma unroll
    for (int i = 0; i < 32; i += 8)
        t[threadIdx.y + i][threadIdx.x] = src[(y0 + threadIdx.y + i) * 256 + x0 + threadIdx.x];
    __syncthreads();
    #pragma unroll
    for (int i = 0; i < 32; i += 8)
        dst[(x0 + threadIdx.y + i) * 256 + y0 + threadIdx.x] = __float2half_rn(t[threadIdx.x][threadIdx.y + i]);
}

// ---------------------------------------------------------------------------
// Fused kernel: 64-row tile, 256 threads, fp16 MMA + ldmatrix, occ 2.
// Produces betas, g_vu, and flash-style output partials g_part/g_mt.
// ---------------------------------------------------------------------------
__global__ void __launch_bounds__(256, 2)
k_fused(const float* __restrict__ x, const float* __restrict__ mask,
        const float* __restrict__ bvec, const float* __restrict__ u,
        float* __restrict__ betas_out)
{
    extern __shared__ char smc[];
    __half* xs  = (__half*)(smc + O_XS);
    float* xw   = (float*)(smc + O_WB);      // fp32 x tile (tail reuse of WB)
    float* bs   = (float*)(smc + O_BS);
    float* us   = (float*)(smc + O_US);
    float* ms   = (float*)(smc + O_MS);
    float* red  = (float*)(smc + O_RED);     // [64][4]
    float* vus  = (float*)(smc + O_VUS);     // [64] masked vu
    float* mtw  = (float*)(smc + O_MTW);     // [2] warp maxes
    float* qs   = (float*)(smc + O_QS);      // [64] q_s
    float4* p4  = (float4*)(smc + O_P4);     // [4][64]

    const uint32_t smb    = smem_u32(smc);
    const uint32_t xs_u32 = smb + O_XS;
    const uint32_t wb_u32 = smb + O_WB;

    const int tid  = threadIdx.x;
    const int lane = tid & 31;
    const int wid  = tid >> 5;
    const int wr   = wid >> 2;       // 0..1: 32-row stripe
    const int wc   = wid & 3;        // 0..3: 64-col quarter
    const int gid  = lane >> 2;
    const int tig  = lane & 3;
    const int row0 = blockIdx.x * TILE_R;

    // ldmatrix per-lane offsets (in halfs)
    const int l7 = lane & 7, l3 = (lane >> 3) & 1, l4 = (lane >> 4) & 1;
    const uint32_t a_off0 = (uint32_t)((wr*32 +  0 + l7 + l3*8) * LDA + l4*8);
    const uint32_t a_off1 = (uint32_t)((wr*32 + 16 + l7 + l3*8) * LDA + l4*8);
    const uint32_t b_off  = (uint32_t)((wc*64 + l7 + l4*8) * LDK + l3*8);

    // headers
    bs[tid] = bvec[tid];
    us[tid] = u[tid];
    if (tid < TILE_R) ms[tid] = mask[row0 + tid];

    // async-prefetch W chunks 0,1; then convert x tile to fp16 smem
    issue_chunk(wb_u32, g_Wh, tid);
    issue_chunk(wb_u32 + CHUNK_B, g_Wh + 32, tid);
    {
        const float* xg = x + (size_t)row0 * DD;
        #pragma unroll
        for (int i = 0; i < 16; i++) {
            int idx = tid + i * 256;             // 4096 float4s
            int row = idx >> 6, c4 = (idx & 63) * 4;
            float4 v = *(const float4*)(xg + row * 256 + c4);
            *(__half2*)(xs + row * LDA + c4)     = __floats2half2_rn(v.x, v.y);
            *(__half2*)(xs + row * LDA + c4 + 2) = __floats2half2_rn(v.z, v.w);
        }
    }

    float acc[2][8][4];

    // ---------------- GEMM1: t = x @ W ----------------
    #pragma unroll
    for (int mt = 0; mt < 2; mt++)
        #pragma unroll
        for (int nt = 0; nt < 8; nt++)
            #pragma unroll
            for (int c = 0; c < 4; c++) acc[mt][nt][c] = 0.0f;

    gemm_loop(acc, g_Wh, xs_u32, wb_u32, a_off0, a_off1, b_off, tid);
    __syncthreads();                 // last-chunk buffer free before Uo prefetch; xs reads done

    // prefetch Uo chunks 0,1 during epilogue1
    issue_chunk(wb_u32, g_Uh, tid);
    issue_chunk(wb_u32 + CHUNK_B, g_Uh + 32, tid);

    // ---------------- epilogue1 (registers): bias + normalize + tanh + vu; v->xs fp16
    {
        float ss[2][2] = {{0,0},{0,0}};
        #pragma unroll
        for (int mt = 0; mt < 2; mt++)
            #pragma unroll
            for (int nt = 0; nt < 8; nt++)
                #pragma unroll
                for (int c = 0; c < 4; c++) {
                    int col = wc*64 + nt*8 + 2*tig + (c & 1);
                    float t = acc[mt][nt][c] + bs[col];
                    acc[mt][nt][c] = t;
                    ss[mt][c>>1] = fmaf(t, t, ss[mt][c>>1]);
                }
        #pragma unroll
        for (int mt = 0; mt < 2; mt++)
            #pragma unroll
            for (int rh = 0; rh < 2; rh++) {
                ss[mt][rh] += __shfl_xor_sync(0xffffffffu, ss[mt][rh], 1);
                ss[mt][rh] += __shfl_xor_sync(0xffffffffu, ss[mt][rh], 2);
            }
        if (tig == 0) {
            #pragma unroll
            for (int mt = 0; mt < 2; mt++)
                #pragma unroll
                for (int rh = 0; rh < 2; rh++)
                    red[(wr*32 + mt*16 + rh*8 + gid)*4 + wc] = ss[mt][rh];
        }
        __syncthreads();
        float invn[2][2];
        #pragma unroll
        for (int mt = 0; mt < 2; mt++)
            #pragma unroll
            for (int rh = 0; rh < 2; rh++) {
                int r = wr*32 + mt*16 + rh*8 + gid;
                float s = red[r*4+0] + red[r*4+1] + red[r*4+2] + red[r*4+3];
                invn[mt][rh] = 1.0f / fmaxf(sqrtf(s), 1e-12f);
            }
        __syncthreads();                     // red free for reuse
        float vu[2][2] = {{0,0},{0,0}};
        #pragma unroll
        for (int mt = 0; mt < 2; mt++)
            #pragma unroll
            for (int nt = 0; nt < 8; nt++) {
                #pragma unroll
                for (int c = 0; c < 4; c++) {
                    int col = wc*64 + nt*8 + 2*tig + (c & 1);
                    float a = acc[mt][nt][c] * invn[mt][c>>1];   // |a| <= 1
                    float v = tanh_fast(a);
                    acc[mt][nt][c] = v;
                    vu[mt][c>>1] = fmaf(v, us[col], vu[mt][c>>1]);
                }
                int cb = wc*64 + nt*8 + 2*tig;
                int r0 = wr*32 + mt*16 + gid;
                *(__half2*)(xs + r0*LDA + cb)     = __floats2half2_rn(acc[mt][nt][0], acc[mt][nt][1]);
                *(__half2*)(xs + (r0+8)*LDA + cb) = __floats2half2_rn(acc[mt][nt][2], acc[mt][nt][3]);
            }
        #pragma unroll
        for (int mt = 0; mt < 2; mt++)
            #pragma unroll
            for (int rh = 0; rh < 2; rh++) {
                vu[mt][rh] += __shfl_xor_sync(0xffffffffu, vu[mt][rh], 1);
                vu[mt][rh] += __shfl_xor_sync(0xffffffffu, vu[mt][rh], 2);
            }
        if (tig == 0) {
            #pragma unroll
            for (int mt = 0; mt < 2; mt++)
                #pragma unroll
                for (int rh = 0; rh < 2; rh++)
                    red[(wr*32 + mt*16 + rh*8 + gid)*4 + wc] = vu[mt][rh];
        }
        __syncthreads();
        if (wc == 0 && tig == 0) {
            #pragma unroll
            for (int mt = 0; mt < 2; mt++)
                #pragma unroll
                for (int rh = 0; rh < 2; rh++) {
                    int r = wr*32 + mt*16 + rh*8 + gid;
                    float s = red[r*4+0] + red[r*4+1] + red[r*4+2] + red[r*4+3];
                    float sm = s * ms[r];
                    g_vu[row0 + r] = sm;
                    vus[r] = sm;
                }
        }
    }

    // ---------------- GEMM2: vuo = v @ Uo ----------------
    #pragma unroll
    for (int mt = 0; mt < 2; mt++)
        #pragma unroll
        for (int nt = 0; nt < 8; nt++)
            #pragma unroll
            for (int c = 0; c < 4; c++) acc[mt][nt][c] = 0.0f;

    gemm_loop(acc, g_Uh, xs_u32, wb_u32, a_off0, a_off1, b_off, tid);

    // ---------------- epilogue2 (registers): mask + softmax over O -> betas,
    //                  then flash-style output partial
    {
        // tile-local vu max (warps 0,1 reduce vus[64])
        if (wid < 2) {
            float vm = vus[lane + wid*32];
            #pragma unroll
            for (int off = 16; off; off >>= 1) vm = fmaxf(vm, __shfl_xor_sync(0xffffffffu, vm, off));
            if (lane == 0) mtw[wid] = vm;
        }

        float mx[2][2] = {{-3.4e38f,-3.4e38f},{-3.4e38f,-3.4e38f}};
        #pragma unroll
        for (int mt = 0; mt < 2; mt++)
            #pragma unroll
            for (int nt = 0; nt < 8; nt++)
                #pragma unroll
                for (int c = 0; c < 4; c++) {
                    int r = wr*32 + mt*16 + ((c>>1)*8) + gid;
                    float v = acc[mt][nt][c] * ms[r];
                    acc[mt][nt][c] = v;
                    mx[mt][c>>1] = fmaxf(mx[mt][c>>1], v);
                }
        #pragma unroll
        for (int mt = 0; mt < 2; mt++)
            #pragma unroll
            for (int rh = 0; rh < 2; rh++) {
                mx[mt][rh] = fmaxf(mx[mt][rh], __shfl_xor_sync(0xffffffffu, mx[mt][rh], 1));
                mx[mt][rh] = fmaxf(mx[mt][rh], __shfl_xor_sync(0xffffffffu, mx[mt][rh], 2));
            }
        __syncthreads();                     // WB dead (all compute done); mtw visible
        // prefetch fp32 x tile into WB for the partial pass
        {
            const float* xg = x + (size_t)row0 * DD;
            #pragma unroll
            for (int i = 0; i < 16; i++) {
                int idx = tid + i * 256;         // 4096 float4s
                cp16(wb_u32 + (uint32_t)idx * 16u, xg + idx * 4);
            }
            CP_COMMIT();
        }
        const float m_t = fmaxf(mtw[0], mtw[1]);
        // q_s = exp(vu_s - m_t) * mask_s   (betas carry their own 1/sum)
        if (tid < TILE_R) qs[tid] = __expf(vus[tid] - m_t) * ms[tid];
        if (tig == 0) {
            #pragma unroll
            for (int mt = 0; mt < 2; mt++)
                #pragma unroll
                for (int rh = 0; rh < 2; rh++)
                    red[(wr*32 + mt*16 + rh*8 + gid)*4 + wc] = mx[mt][rh];
        }
        __syncthreads();
        float mxf[2][2];
        #pragma unroll
        for (int mt = 0; mt < 2; mt++)
            #pragma unroll
            for (int rh = 0; rh < 2; rh++) {
                int r = wr*32 + mt*16 + rh*8 + gid;
                mxf[mt][rh] = fmaxf(fmaxf(red[r*4+0], red[r*4+1]), fmaxf(red[r*4+2], red[r*4+3]));
            }
        __syncthreads();
        float sume[2][2] = {{0,0},{0,0}};
        #pragma unroll
        for (int mt = 0; mt < 2; mt++)
            #pragma unroll
            for (int nt = 0; nt < 8; nt++)
                #pragma unroll
                for (int c = 0; c < 4; c++) {
                    int r = wr*32 + mt*16 + ((c>>1)*8) + gid;
                    float e = __expf(acc[mt][nt][c] - mxf[mt][c>>1]) * ms[r];
                    acc[mt][nt][c] = e;
                    sume[mt][c>>1] += e;
                }
        #pragma unroll
        for (int mt = 0; mt < 2; mt++)
            #pragma unroll
            for (int rh = 0; rh < 2; rh++) {
                sume[mt][rh] += __shfl_xor_sync(0xffffffffu, sume[mt][rh], 1);
                sume[mt][rh] += __shfl_xor_sync(0xffffffffu, sume[mt][rh], 2);
            }
        if (tig == 0) {
            #pragma unroll
            for (int mt = 0; mt < 2; mt++)
                #pragma unroll
                for (int rh = 0; rh < 2; rh++)
                    red[(wr*32 + mt*16 + rh*8 + gid)*4 + wc] = sume[mt][rh];
        }
        __syncthreads();
        float* bo = betas_out + (size_t)row0 * OO;
        #pragma unroll
        for (int mt = 0; mt < 2; mt++) {
            float inv[2];
            #pragma unroll
            for (int rh = 0; rh < 2; rh++) {
                int r = wr*32 + mt*16 + rh*8 + gid;
                float s = red[r*4+0] + red[r*4+1] + red[r*4+2] + red[r*4+3];
                inv[rh] = (s == 0.0f) ? 1.0f : __fdividef(1.0f, s);
            }
            int r0 = wr*32 + mt*16 + gid;
            #pragma unroll
            for (int nt = 0; nt < 8; nt++) {
                int cb = wc*64 + nt*8 + 2*tig;
                *(float2*)(bo + (size_t)r0 * OO + cb)     = make_float2(acc[mt][nt][0]*inv[0], acc[mt][nt][1]*inv[0]);
                *(float2*)(bo + (size_t)(r0+8) * OO + cb) = make_float2(acc[mt][nt][2]*inv[1], acc[mt][nt][3]*inv[1]);
            }
        }
        CP_WAIT0();                          // x tile in WB landed (per-thread)
        __syncthreads();                     // betas + qs + xw visible block-wide

        // ---- in-kernel output partial: P_t[o] = sum_r qs[r]*betas[r][o]*x[r][o]
        {
            const int o4 = (tid & 63) * 4;
            const int rq = tid >> 6;
            float4 pa = make_float4(0.f, 0.f, 0.f, 0.f);
            #pragma unroll 4
            for (int r = rq; r < TILE_R; r += 4) {
                float q = qs[r];
                if (q != 0.0f) {
                    float4 xv = *(const float4*)(xw + r * OO + o4);
                    float4 bv = *(const float4*)(betas_out + ((size_t)(row0 + r)) * OO + o4);
                    pa.x = fmaf(q * xv.x, bv.x, pa.x);
                    pa.y = fmaf(q * xv.y, bv.y, pa.y);
                    pa.z = fmaf(q * xv.z, bv.z, pa.z);
                    pa.w = fmaf(q * xv.w, bv.w, pa.w);
                }
            }
            p4[rq * 64 + (tid & 63)] = pa;
            __syncthreads();
            if (tid < 64) {
                float4 a0 = p4[tid], a1 = p4[64+tid], a2 = p4[128+tid], a3 = p4[192+tid];
                float4 s = make_float4(a0.x+a1.x+a2.x+a3.x, a0.y+a1.y+a2.y+a3.y,
                                       a0.z+a1.z+a2.z+a3.z, a0.w+a1.w+a2.w+a3.w);
                *(float4*)&g_part[(size_t)blockIdx.x * OO + tid * 4] = s;
            }
            if (tid == 0) g_mt[blockIdx.x] = m_t;
        }
    }
}

// ---------------------------------------------------------------------------
// Final: alphas = masked softmax of g_vu over S, per batch, then
// out[b][o] = sum_t g_part[t][o] * exp(m_t - M_b) / Z_b   (16 tiles per batch)
// ---------------------------------------------------------------------------
__global__ __launch_bounds__(1024)
void k_final(const float* __restrict__ mask, float* __restrict__ alphas,
             float* __restrict__ out)
{
    __shared__ float redA[32];
    __shared__ float redB[32];
    __shared__ float sc[16];
    const int b = blockIdx.x;
    const int s = threadIdx.x;
    const int lane = s & 31, wid = s >> 5;

    float val = g_vu[b*SS + s];
    float m   = mask[b*SS + s];

    float wm = val;
    #pragma unroll
    for (int off = 16; off; off >>= 1) wm = fmaxf(wm, __shfl_xor_sync(0xffffffffu, wm, off));
    if (lane == 0) redA[wid] = wm;
    __syncthreads();
    if (wid == 0) {
        float t = redA[lane];
        #pragma unroll
        for (int off = 16; off; off >>= 1) t = fmaxf(t, __shfl_xor_sync(0xffffffffu, t, off));
        if (lane == 0) redA[0] = t;
    }
    __syncthreads();
    float mx = redA[0];

    float e = __expf(val - mx) * m;
    float wsm = e;
    #pragma unroll
    for (int off = 16; off; off >>= 1) wsm += __shfl_xor_sync(0xffffffffu, wsm, off);
    if (lane == 0) redB[wid] = wsm;
    __syncthreads();
    if (wid == 0) {
        float t = redB[lane];
        #pragma unroll
        for (int off = 16; off; off >>= 1) t += __shfl_xor_sync(0xffffffffu, t, off);
        if (lane == 0) redB[0] = t;
    }
    __syncthreads();
    float sum = redB[0];
    float inv = (sum == 0.0f) ? 1.0f : (1.0f / sum);
    alphas[b*SS + s] = e * inv;

    // output tail: rescale per-tile partials
    if (s < 16) sc[s] = __expf(g_mt[b*16 + s] - mx) * inv;
    __syncthreads();
    if (s < OO) {
        float acc = 0.0f;
        #pragma unroll
        for (int t = 0; t < 16; t++)
            acc += g_part[((size_t)(b*16 + t)) * OO + s] * sc[t];
        out[b*OO + s] = acc;
    }
}

// ---------------------------------------------------------------------------
extern "C" void kernel_launch(void* const* d_in, const int* in_sizes, int n_in,
                              void* d_out, int out_size)
{
    const float* x    = (const float*)d_in[0];   // [B,S,D]
    const float* mask = (const float*)d_in[1];   // [B,S]
    const float* W    = (const float*)d_in[2];   // [D,A]
    const float* bv   = (const float*)d_in[3];   // [A]
    const float* u    = (const float*)d_in[4];   // [A]
    const float* Uo   = (const float*)d_in[5];   // [A,O]

    float* out    = (float*)d_out;               // [B,O]
    float* alphas = out + BB * OO;               // [B,S]
    float* betas  = alphas + BB * SS;            // [B,S,O]

    cudaFuncSetAttribute(k_fused, cudaFuncAttributeMaxDynamicSharedMemorySize, SMEM_BYTES);

    dim3 tg(8, 8, 2), tb(32, 8);
    k_prep<<<tg, tb>>>(W, Uo);
    k_fused<<<NROWS / TILE_R, 256, SMEM_BYTES>>>(x, mask, bv, u, betas);
    k_final<<<BB, 1024>>>(mask, alphas, out);
}

// round 15
// speedup vs baseline: 1.0029x; 1.0029x over previous
#include <cuda_runtime.h>
#include <cuda_fp16.h>
#include <math.h>
#include <stdint.h>

// Shapes (fixed)
#define BB 128
#define SS 1024
#define DD 256
#define AA 256
#define OO 256
#define NROWS (BB*SS)

#define TILE_R 64
#define LDA 264            // xs row stride in halfs (528B) -> conflict-free
#define LDK 40             // weight row stride in halfs (80B) -> conflict-free
#define CHUNK_B (256*LDK*2)   // 20480 bytes per 32-k weight chunk
#define NSTAGE 3

// smem byte offsets
#define O_XS   0               // 64*264*2 = 33792
#define O_WB   33792           // 3*20480 = 61440
#define O_BS   95232           // 256 f32
#define O_US   96256           // 256 f32
#define O_MS   97280           // 64 f32
#define O_RED  97536           // 64*4 f32
#define O_VUS  98560           // 64 f32
#define O_MTW  98816           // 2 f32 (+pad)
#define O_QS   98832           // 64 f32
#define O_P4   99088           // 4*64 float4 = 4096
#define O_RED2 103184          // 64*4 f32 (second reduction buffer)
#define SMEM_BYTES 104208      // rounds to 106496; 2 CTAs = 212992 < 228KB -> occ 2

// Scratch
__device__ float g_vu[NROWS];
__device__ float g_part[NROWS/TILE_R * OO];   // per-tile output partials
__device__ float g_mt[NROWS/TILE_R];          // per-tile local max
__device__ __half g_Wh[DD * AA];    // W  transposed to [a][d], fp16
__device__ __half g_Uh[AA * OO];    // Uo transposed to [o][a], fp16

// ---------------------------------------------------------------------------
__device__ __forceinline__ uint32_t smem_u32(const void* p) {
    uint32_t a;
    asm("{ .reg .u64 t; cvta.to.shared.u64 t, %1; cvt.u32.u64 %0, t; }" : "=r"(a) : "l"(p));
    return a;
}
__device__ __forceinline__ void cp16(uint32_t dst, const void* src) {
    asm volatile("cp.async.cg.shared.global [%0], [%1], 16;" :: "r"(dst), "l"(src));
}
#define CP_COMMIT() asm volatile("cp.async.commit_group;" ::: "memory")
#define CP_WAIT0()  asm volatile("cp.async.wait_group 0;" ::: "memory")
#define CP_WAIT1()  asm volatile("cp.async.wait_group 1;" ::: "memory")

__device__ __forceinline__ void mma16(float* c, const uint32_t* a, uint32_t b0, uint32_t b1) {
    asm("mma.sync.aligned.m16n8k16.row.col.f32.f16.f16.f32 "
        "{%0,%1,%2,%3}, {%4,%5,%6,%7}, {%8,%9}, {%0,%1,%2,%3};"
        : "+f"(c[0]), "+f"(c[1]), "+f"(c[2]), "+f"(c[3])
        : "r"(a[0]), "r"(a[1]), "r"(a[2]), "r"(a[3]), "r"(b0), "r"(b1));
}
__device__ __forceinline__ void ldm4(uint32_t* d, uint32_t addr) {
    asm volatile("ldmatrix.sync.aligned.m8n8.x4.shared.b16 {%0,%1,%2,%3}, [%4];"
        : "=r"(d[0]), "=r"(d[1]), "=r"(d[2]), "=r"(d[3]) : "r"(addr));
}
__device__ __forceinline__ float tanh_fast(float a) {
    float v;
    asm("tanh.approx.f32 %0, %1;" : "=f"(v) : "f"(a));
    return v;
}

// issue one 32k x 256n fp16 chunk: 256 threads, 4 cp16 each
__device__ __forceinline__ void issue_chunk(uint32_t dst, const __half* gsrc, int tid) {
    const __half* s = gsrc + tid * 256;
    uint32_t d = dst + (uint32_t)(tid * LDK * 2);
    #pragma unroll
    for (int p = 0; p < 4; p++) cp16(d + p * 16, s + p * 8);
    CP_COMMIT();
}

// one 32-k chunk of MMAs (two 16-k steps), ldmatrix fragment loads
__device__ __forceinline__ void compute_chunk(float acc[2][8][4],
        uint32_t xs_u32, uint32_t wb_cur, int kbase,
        uint32_t a_off0, uint32_t a_off1, uint32_t b_off)
{
    #pragma unroll
    for (int ks = 0; ks < 2; ks++) {
        const uint32_t kb2 = (uint32_t)(kbase + ks * 16) * 2u;
        uint32_t a0[4], a1[4];
        ldm4(a0, xs_u32 + a_off0 * 2u + kb2);
        ldm4(a1, xs_u32 + a_off1 * 2u + kb2);
        #pragma unroll
        for (int p = 0; p < 4; p++) {
            uint32_t b[4];
            ldm4(b, wb_cur + (b_off + (uint32_t)(p * 16 * LDK)) * 2u + (uint32_t)(ks * 32));
            mma16(acc[0][2*p],   a0, b[0], b[1]);
            mma16(acc[1][2*p],   a1, b[0], b[1]);
            mma16(acc[0][2*p+1], a0, b[2], b[3]);
            mma16(acc[1][2*p+1], a1, b[2], b[3]);
        }
    }
}

// 8 chunks, 3-stage ring, ONE sync per chunk. Chunks 0,1 pre-issued into bufs 0,1.
__device__ __forceinline__ void gemm_loop(float acc[2][8][4], const __half* __restrict__ gW,
        uint32_t xs_u32, uint32_t wb_u32,
        uint32_t a_off0, uint32_t a_off1, uint32_t b_off, int tid)
{
    for (int kc = 0; kc < 8; kc++) {
        if (kc < 7) CP_WAIT1(); else CP_WAIT0();
        __syncthreads();                       // chunk kc visible; buf (kc+2)%3 free
        if (kc + 2 < 8)
            issue_chunk(wb_u32 + (uint32_t)((kc + 2) % NSTAGE) * CHUNK_B,
                        gW + (kc + 2) * 32, tid);
        compute_chunk(acc, xs_u32, wb_u32 + (uint32_t)(kc % NSTAGE) * CHUNK_B,
                      kc * 32, a_off0, a_off1, b_off);
    }
}

// ---------------------------------------------------------------------------
// Transpose + fp16 convert: g_Wh[a][d] = W[d][a], g_Uh[o][a] = Uo[a][o]
// ---------------------------------------------------------------------------
__global__ void k_prep(const float* __restrict__ W, const float* __restrict__ Uo)
{
    __shared__ float t[32][33];
    const float* src = blockIdx.z ? Uo : W;
    __half* dst = blockIdx.z ? g_Uh : g_Wh;
    int x0 = blockIdx.x * 32, y0 = blockIdx.y * 32;
    #pragma unroll
    for (int i = 0; i < 32; i += 8)
        t[threadIdx.y + i][threadIdx.x] = src[(y0 + threadIdx.y + i) * 256 + x0 + threadIdx.x];
    __syncthreads();
    #pragma unroll
    for (int i = 0; i < 32; i += 8)
        dst[(x0 + threadIdx.y + i) * 256 + y0 + threadIdx.x] = __float2half_rn(t[threadIdx.x][threadIdx.y + i]);
}

// ---------------------------------------------------------------------------
// Fused kernel: 64-row tile, 256 threads, fp16 MMA + ldmatrix, occ 2.
// Produces betas, g_vu, and flash-style output partials g_part/g_mt.
// ---------------------------------------------------------------------------
__global__ void __launch_bounds__(256, 2)
k_fused(const float* __restrict__ x, const float* __restrict__ mask,
        const float* __restrict__ bvec, const float* __restrict__ u,
        float* __restrict__ betas_out)
{
    extern __shared__ char smc[];
    __half* xs   = (__half*)(smc + O_XS);
    float* bs    = (float*)(smc + O_BS);
    float* us    = (float*)(smc + O_US);
    float* ms    = (float*)(smc + O_MS);
    float* red   = (float*)(smc + O_RED);     // [64][4]
    float* red2  = (float*)(smc + O_RED2);    // [64][4]
    float* vus   = (float*)(smc + O_VUS);     // [64] masked vu
    float* mtw   = (float*)(smc + O_MTW);     // [2] warp maxes
    float* qs    = (float*)(smc + O_QS);      // [64] q_s
    float4* p4   = (float4*)(smc + O_P4);     // [4][64]

    const uint32_t smb    = smem_u32(smc);
    const uint32_t xs_u32 = smb + O_XS;
    const uint32_t wb_u32 = smb + O_WB;

    const int tid  = threadIdx.x;
    const int lane = tid & 31;
    const int wid  = tid >> 5;
    const int wr   = wid >> 2;       // 0..1: 32-row stripe
    const int wc   = wid & 3;        // 0..3: 64-col quarter
    const int gid  = lane >> 2;
    const int tig  = lane & 3;
    const int row0 = blockIdx.x * TILE_R;

    // ldmatrix per-lane offsets (in halfs)
    const int l7 = lane & 7, l3 = (lane >> 3) & 1, l4 = (lane >> 4) & 1;
    const uint32_t a_off0 = (uint32_t)((wr*32 +  0 + l7 + l3*8) * LDA + l4*8);
    const uint32_t a_off1 = (uint32_t)((wr*32 + 16 + l7 + l3*8) * LDA + l4*8);
    const uint32_t b_off  = (uint32_t)((wc*64 + l7 + l4*8) * LDK + l3*8);

    // headers
    bs[tid] = bvec[tid];
    us[tid] = u[tid];
    if (tid < TILE_R) ms[tid] = mask[row0 + tid];

    // async-prefetch W chunks 0,1; then convert x tile to fp16 smem
    issue_chunk(wb_u32, g_Wh, tid);
    issue_chunk(wb_u32 + CHUNK_B, g_Wh + 32, tid);
    {
        const float* xg = x + (size_t)row0 * DD;
        #pragma unroll
        for (int i = 0; i < 16; i++) {
            int idx = tid + i * 256;             // 4096 float4s
            int row = idx >> 6, c4 = (idx & 63) * 4;
            float4 v = *(const float4*)(xg + row * 256 + c4);
            *(__half2*)(xs + row * LDA + c4)     = __floats2half2_rn(v.x, v.y);
            *(__half2*)(xs + row * LDA + c4 + 2) = __floats2half2_rn(v.z, v.w);
        }
    }

    float acc[2][8][4];

    // ---------------- GEMM1: t = x @ W ----------------
    #pragma unroll
    for (int mt = 0; mt < 2; mt++)
        #pragma unroll
        for (int nt = 0; nt < 8; nt++)
            #pragma unroll
            for (int c = 0; c < 4; c++) acc[mt][nt][c] = 0.0f;

    gemm_loop(acc, g_Wh, xs_u32, wb_u32, a_off0, a_off1, b_off, tid);
    __syncthreads();                 // last-chunk buffer free before Uo prefetch; xs reads done

    // prefetch Uo chunks 0,1 during epilogue1
    issue_chunk(wb_u32, g_Uh, tid);
    issue_chunk(wb_u32 + CHUNK_B, g_Uh + 32, tid);

    // ---------------- epilogue1 (registers): bias + normalize + tanh + vu; v->xs fp16
    {
        float ss[2][2] = {{0,0},{0,0}};
        #pragma unroll
        for (int mt = 0; mt < 2; mt++)
            #pragma unroll
            for (int nt = 0; nt < 8; nt++)
                #pragma unroll
                for (int c = 0; c < 4; c++) {
                    int col = wc*64 + nt*8 + 2*tig + (c & 1);
                    float t = acc[mt][nt][c] + bs[col];
                    acc[mt][nt][c] = t;
                    ss[mt][c>>1] = fmaf(t, t, ss[mt][c>>1]);
                }
        #pragma unroll
        for (int mt = 0; mt < 2; mt++)
            #pragma unroll
            for (int rh = 0; rh < 2; rh++) {
                ss[mt][rh] += __shfl_xor_sync(0xffffffffu, ss[mt][rh], 1);
                ss[mt][rh] += __shfl_xor_sync(0xffffffffu, ss[mt][rh], 2);
            }
        if (tig == 0) {
            #pragma unroll
            for (int mt = 0; mt < 2; mt++)
                #pragma unroll
                for (int rh = 0; rh < 2; rh++)
                    red[(wr*32 + mt*16 + rh*8 + gid)*4 + wc] = ss[mt][rh];
        }
        __syncthreads();
        float invn[2][2];
        #pragma unroll
        for (int mt = 0; mt < 2; mt++)
            #pragma unroll
            for (int rh = 0; rh < 2; rh++) {
                int r = wr*32 + mt*16 + rh*8 + gid;
                float s = red[r*4+0] + red[r*4+1] + red[r*4+2] + red[r*4+3];
                invn[mt][rh] = 1.0f / fmaxf(sqrtf(s), 1e-12f);
            }
        // no barrier needed: vu goes to red2
        float vu[2][2] = {{0,0},{0,0}};
        #pragma unroll
        for (int mt = 0; mt < 2; mt++)
            #pragma unroll
            for (int nt = 0; nt < 8; nt++) {
                #pragma unroll
                for (int c = 0; c < 4; c++) {
                    int col = wc*64 + nt*8 + 2*tig + (c & 1);
                    float a = acc[mt][nt][c] * invn[mt][c>>1];   // |a| <= 1
                    float v = tanh_fast(a);
                    acc[mt][nt][c] = v;
                    vu[mt][c>>1] = fmaf(v, us[col], vu[mt][c>>1]);
                }
                int cb = wc*64 + nt*8 + 2*tig;
                int r0 = wr*32 + mt*16 + gid;
                *(__half2*)(xs + r0*LDA + cb)     = __floats2half2_rn(acc[mt][nt][0], acc[mt][nt][1]);
                *(__half2*)(xs + (r0+8)*LDA + cb) = __floats2half2_rn(acc[mt][nt][2], acc[mt][nt][3]);
            }
        #pragma unroll
        for (int mt = 0; mt < 2; mt++)
            #pragma unroll
            for (int rh = 0; rh < 2; rh++) {
                vu[mt][rh] += __shfl_xor_sync(0xffffffffu, vu[mt][rh], 1);
                vu[mt][rh] += __shfl_xor_sync(0xffffffffu, vu[mt][rh], 2);
            }
        if (tig == 0) {
            #pragma unroll
            for (int mt = 0; mt < 2; mt++)
                #pragma unroll
                for (int rh = 0; rh < 2; rh++)
                    red2[(wr*32 + mt*16 + rh*8 + gid)*4 + wc] = vu[mt][rh];
        }
        __syncthreads();
        if (wc == 0 && tig == 0) {
            #pragma unroll
            for (int mt = 0; mt < 2; mt++)
                #pragma unroll
                for (int rh = 0; rh < 2; rh++) {
                    int r = wr*32 + mt*16 + rh*8 + gid;
                    float s = red2[r*4+0] + red2[r*4+1] + red2[r*4+2] + red2[r*4+3];
                    float sm = s * ms[r];
                    g_vu[row0 + r] = sm;
                    vus[r] = sm;
                }
        }
    }

    // ---------------- GEMM2: vuo = v @ Uo ----------------
    #pragma unroll
    for (int mt = 0; mt < 2; mt++)
        #pragma unroll
        for (int nt = 0; nt < 8; nt++)
            #pragma unroll
            for (int c = 0; c < 4; c++) acc[mt][nt][c] = 0.0f;

    gemm_loop(acc, g_Uh, xs_u32, wb_u32, a_off0, a_off1, b_off, tid);

    // ---------------- epilogue2 (registers): mask + softmax over O -> betas,
    //                  then flash-style output partial
    {
        // tile-local vu max (warps 0,1 reduce vus[64])
        if (wid < 2) {
            float vm = vus[lane + wid*32];
            #pragma unroll
            for (int off = 16; off; off >>= 1) vm = fmaxf(vm, __shfl_xor_sync(0xffffffffu, vm, off));
            if (lane == 0) mtw[wid] = vm;
        }

        float mx[2][2] = {{-3.4e38f,-3.4e38f},{-3.4e38f,-3.4e38f}};
        #pragma unroll
        for (int mt = 0; mt < 2; mt++)
            #pragma unroll
            for (int nt = 0; nt < 8; nt++)
                #pragma unroll
                for (int c = 0; c < 4; c++) {
                    int r = wr*32 + mt*16 + ((c>>1)*8) + gid;
                    float v = acc[mt][nt][c] * ms[r];
                    acc[mt][nt][c] = v;
                    mx[mt][c>>1] = fmaxf(mx[mt][c>>1], v);
                }
        #pragma unroll
        for (int mt = 0; mt < 2; mt++)
            #pragma unroll
            for (int rh = 0; rh < 2; rh++) {
                mx[mt][rh] = fmaxf(mx[mt][rh], __shfl_xor_sync(0xffffffffu, mx[mt][rh], 1));
                mx[mt][rh] = fmaxf(mx[mt][rh], __shfl_xor_sync(0xffffffffu, mx[mt][rh], 2));
            }
        __syncthreads();                     // red/red2 (ep1) reads done; mtw visible
        const float m_t = fmaxf(mtw[0], mtw[1]);
        // q_s = exp(vu_s - m_t) * mask_s   (betas carry their own 1/sum)
        if (tid < TILE_R) qs[tid] = __expf(vus[tid] - m_t) * ms[tid];
        if (tig == 0) {
            #pragma unroll
            for (int mt = 0; mt < 2; mt++)
                #pragma unroll
                for (int rh = 0; rh < 2; rh++)
                    red[(wr*32 + mt*16 + rh*8 + gid)*4 + wc] = mx[mt][rh];
        }
        __syncthreads();
        float mxf[2][2];
        #pragma unroll
        for (int mt = 0; mt < 2; mt++)
            #pragma unroll
            for (int rh = 0; rh < 2; rh++) {
                int r = wr*32 + mt*16 + rh*8 + gid;
                mxf[mt][rh] = fmaxf(fmaxf(red[r*4+0], red[r*4+1]), fmaxf(red[r*4+2], red[r*4+3]));
            }
        // no barrier: sume goes to red2
        float sume[2][2] = {{0,0},{0,0}};
        #pragma unroll
        for (int mt = 0; mt < 2; mt++)
            #pragma unroll
            for (int nt = 0; nt < 8; nt++)
                #pragma unroll
                for (int c = 0; c < 4; c++) {
                    int r = wr*32 + mt*16 + ((c>>1)*8) + gid;
                    float e = __expf(acc[mt][nt][c] - mxf[mt][c>>1]) * ms[r];
                    acc[mt][nt][c] = e;
                    sume[mt][c>>1] += e;
                }
        #pragma unroll
        for (int mt = 0; mt < 2; mt++)
            #pragma unroll
            for (int rh = 0; rh < 2; rh++) {
                sume[mt][rh] += __shfl_xor_sync(0xffffffffu, sume[mt][rh], 1);
                sume[mt][rh] += __shfl_xor_sync(0xffffffffu, sume[mt][rh], 2);
            }
        if (tig == 0) {
            #pragma unroll
            for (int mt = 0; mt < 2; mt++)
                #pragma unroll
                for (int rh = 0; rh < 2; rh++)
                    red2[(wr*32 + mt*16 + rh*8 + gid)*4 + wc] = sume[mt][rh];
        }
        __syncthreads();
        float* bo = betas_out + (size_t)row0 * OO;
        #pragma unroll
        for (int mt = 0; mt < 2; mt++) {
            float inv[2];
            #pragma unroll
            for (int rh = 0; rh < 2; rh++) {
                int r = wr*32 + mt*16 + rh*8 + gid;
                float s = red2[r*4+0] + red2[r*4+1] + red2[r*4+2] + red2[r*4+3];
                inv[rh] = (s == 0.0f) ? 1.0f : __fdividef(1.0f, s);
            }
            int r0 = wr*32 + mt*16 + gid;
            #pragma unroll
            for (int nt = 0; nt < 8; nt++) {
                int cb = wc*64 + nt*8 + 2*tig;
                *(float2*)(bo + (size_t)r0 * OO + cb)     = make_float2(acc[mt][nt][0]*inv[0], acc[mt][nt][1]*inv[0]);
                *(float2*)(bo + (size_t)(r0+8) * OO + cb) = make_float2(acc[mt][nt][2]*inv[1], acc[mt][nt][3]*inv[1]);
            }
        }
        __syncthreads();                     // betas (global, block-visible) + qs ready

        // ---- in-kernel output partial: P_t[o] = sum_r qs[r]*betas[r][o]*x[r][o]
        {
            const int o4 = (tid & 63) * 4;
            const int rq = tid >> 6;
            float4 pa = make_float4(0.f, 0.f, 0.f, 0.f);
            #pragma unroll 4
            for (int r = rq; r < TILE_R; r += 4) {
                float q = qs[r];
                if (q != 0.0f) {
                    size_t base = ((size_t)(row0 + r)) * OO + o4;
                    float4 xv = *(const float4*)(x + base);
                    float4 bv = *(const float4*)(betas_out + base);
                    pa.x = fmaf(q * xv.x, bv.x, pa.x);
                    pa.y = fmaf(q * xv.y, bv.y, pa.y);
                    pa.z = fmaf(q * xv.z, bv.z, pa.z);
                    pa.w = fmaf(q * xv.w, bv.w, pa.w);
                }
            }
            p4[rq * 64 + (tid & 63)] = pa;
            __syncthreads();
            if (tid < 64) {
                float4 a0 = p4[tid], a1 = p4[64+tid], a2 = p4[128+tid], a3 = p4[192+tid];
                float4 s = make_float4(a0.x+a1.x+a2.x+a3.x, a0.y+a1.y+a2.y+a3.y,
                                       a0.z+a1.z+a2.z+a3.z, a0.w+a1.w+a2.w+a3.w);
                *(float4*)&g_part[(size_t)blockIdx.x * OO + tid * 4] = s;
            }
            if (tid == 0) g_mt[blockIdx.x] = m_t;
        }
    }
}

// ---------------------------------------------------------------------------
// Final: alphas = masked softmax of g_vu over S, per batch, then
// out[b][o] = sum_t g_part[t][o] * exp(m_t - M_b) / Z_b   (16 tiles per batch)
// ---------------------------------------------------------------------------
__global__ __launch_bounds__(1024)
void k_final(const float* __restrict__ mask, float* __restrict__ alphas,
             float* __restrict__ out)
{
    __shared__ float redA[32];
    __shared__ float redB[32];
    __shared__ float sc[16];
    const int b = blockIdx.x;
    const int s = threadIdx.x;
    const int lane = s & 31, wid = s >> 5;

    float val = g_vu[b*SS + s];
    float m   = mask[b*SS + s];

    float wm = val;
    #pragma unroll
    for (int off = 16; off; off >>= 1) wm = fmaxf(wm, __shfl_xor_sync(0xffffffffu, wm, off));
    if (lane == 0) redA[wid] = wm;
    __syncthreads();
    if (wid == 0) {
        float t = redA[lane];
        #pragma unroll
        for (int off = 16; off; off >>= 1) t = fmaxf(t, __shfl_xor_sync(0xffffffffu, t, off));
        if (lane == 0) redA[0] = t;
    }
    __syncthreads();
    float mx = redA[0];

    float e = __expf(val - mx) * m;
    float wsm = e;
    #pragma unroll
    for (int off = 16; off; off >>= 1) wsm += __shfl_xor_sync(0xffffffffu, wsm, off);
    if (lane == 0) redB[wid] = wsm;
    __syncthreads();
    if (wid == 0) {
        float t = redB[lane];
        #pragma unroll
        for (int off = 16; off; off >>= 1) t += __shfl_xor_sync(0xffffffffu, t, off);
        if (lane == 0) redB[0] = t;
    }
    __syncthreads();
    float sum = redB[0];
    float inv = (sum == 0.0f) ? 1.0f : (1.0f / sum);
    alphas[b*SS + s] = e * inv;

    // output tail: rescale per-tile partials
    if (s < 16) sc[s] = __expf(g_mt[b*16 + s] - mx) * inv;
    __syncthreads();
    if (s < OO) {
        float acc = 0.0f;
        #pragma unroll
        for (int t = 0; t < 16; t++)
            acc += g_part[((size_t)(b*16 + t)) * OO + s] * sc[t];
        out[b*OO + s] = acc;
    }
}

// ---------------------------------------------------------------------------
extern "C" void kernel_launch(void* const* d_in, const int* in_sizes, int n_in,
                              void* d_out, int out_size)
{
    const float* x    = (const float*)d_in[0];   // [B,S,D]
    const float* mask = (const float*)d_in[1];   // [B,S]
    const float* W    = (const float*)d_in[2];   // [D,A]
    const float* bv   = (const float*)d_in[3];   // [A]
    const float* u    = (const float*)d_in[4];   // [A]
    const float* Uo   = (const float*)d_in[5];   // [A,O]

    float* out    = (float*)d_out;               // [B,O]
    float* alphas = out + BB * OO;               // [B,S]
    float* betas  = alphas + BB * SS;            // [B,S,O]

    cudaFuncSetAttribute(k_fused, cudaFuncAttributeMaxDynamicSharedMemorySize, SMEM_BYTES);

    dim3 tg(8, 8, 2), tb(32, 8);
    k_prep<<<tg, tb>>>(W, Uo);
    k_fused<<<NROWS / TILE_R, 256, SMEM_BYTES>>>(x, mask, bv, u, betas);
    k_final<<<BB, 1024>>>(mask, alphas, out);
}

// round 16
// speedup vs baseline: 1.2099x; 1.2064x over previous
#include <cuda_runtime.h>
#include <cuda_fp16.h>
#include <math.h>
#include <stdint.h>

// Shapes (fixed)
#define BB 128
#define SS 1024
#define DD 256
#define AA 256
#define OO 256
#define NROWS (BB*SS)

#define TILE_R 128
#define NTILE (NROWS/TILE_R)   // 1024
#define TPB 8                  // tiles per batch
#define LDA 264                // xs row stride in halfs (528B = 33*16) -> conflict-free
#define LDK 40                 // weight row stride in halfs (80B = 5*16) -> conflict-free
#define CHUNK_B (256*LDK*2)    // 20480 bytes per 32-k weight chunk
#define NSTAGE 4

// smem byte offsets
#define O_XS   0               // 128*264*2 = 67584
#define O_WB   67584           // 4*20480 = 81920
#define O_BS   149504          // 256 f32
#define O_US   150528          // 256 f32
#define O_MS   151552          // 128 f32
#define O_RED  152064          // 128*2 f32 = 1024
#define O_RED2 153088          // 128*2 f32 = 1024
#define O_VUS  154112          // 128 f32
#define O_MTW  154624          // 4 f32
#define O_QS   154640          // 128 f32
#define O_P4   155152          // 8*64 float4 = 8192
#define SMEM_BYTES 163344      // < 228KB, occ 1 (16 warps/SM)

// Scratch
__device__ float g_vu[NROWS];
__device__ float g_part[NTILE * OO];   // per-tile output partials
__device__ float g_mt[NTILE];          // per-tile local max
__device__ __half g_Wh[DD * AA];       // W  transposed to [a][d], fp16
__device__ __half g_Uh[AA * OO];       // Uo transposed to [o][a], fp16

// ---------------------------------------------------------------------------
__device__ __forceinline__ uint32_t smem_u32(const void* p) {
    uint32_t a;
    asm("{ .reg .u64 t; cvta.to.shared.u64 t, %1; cvt.u32.u64 %0, t; }" : "=r"(a) : "l"(p));
    return a;
}
__device__ __forceinline__ void cp16(uint32_t dst, const void* src) {
    asm volatile("cp.async.cg.shared.global [%0], [%1], 16;" :: "r"(dst), "l"(src));
}
#define CP_COMMIT() asm volatile("cp.async.commit_group;" ::: "memory")
#define CP_WAIT0()  asm volatile("cp.async.wait_group 0;" ::: "memory")
#define CP_WAIT1()  asm volatile("cp.async.wait_group 1;" ::: "memory")
#define CP_WAIT2()  asm volatile("cp.async.wait_group 2;" ::: "memory")

__device__ __forceinline__ void mma16(float* c, const uint32_t* a, uint32_t b0, uint32_t b1) {
    asm("mma.sync.aligned.m16n8k16.row.col.f32.f16.f16.f32 "
        "{%0,%1,%2,%3}, {%4,%5,%6,%7}, {%8,%9}, {%0,%1,%2,%3};"
        : "+f"(c[0]), "+f"(c[1]), "+f"(c[2]), "+f"(c[3])
        : "r"(a[0]), "r"(a[1]), "r"(a[2]), "r"(a[3]), "r"(b0), "r"(b1));
}
__device__ __forceinline__ void ldm4(uint32_t* d, uint32_t addr) {
    asm volatile("ldmatrix.sync.aligned.m8n8.x4.shared.b16 {%0,%1,%2,%3}, [%4];"
        : "=r"(d[0]), "=r"(d[1]), "=r"(d[2]), "=r"(d[3]) : "r"(addr));
}
__device__ __forceinline__ float tanh_fast(float a) {
    float v;
    asm("tanh.approx.f32 %0, %1;" : "=f"(v) : "f"(a));
    return v;
}

// issue one 32k x 256n fp16 chunk: 512 threads, 2 cp16 each
__device__ __forceinline__ void issue_chunk(uint32_t dst, const __half* gsrc, int tid) {
    int n = tid >> 1, p = tid & 1;
    const __half* s = gsrc + n * 256 + p * 16;
    uint32_t d = dst + (uint32_t)(n * LDK * 2 + p * 32);
    cp16(d, s);
    cp16(d + 16, s + 8);
    CP_COMMIT();
}

// one 32-k chunk of MMAs (two 16-k steps); warp tile 16 rows x 128 cols
__device__ __forceinline__ void compute_chunk(float acc[16][4],
        uint32_t xs_u32, uint32_t wb_cur, int kbase,
        uint32_t a_off, uint32_t b_off)
{
    #pragma unroll
    for (int ks = 0; ks < 2; ks++) {
        const uint32_t kb2 = (uint32_t)(kbase + ks * 16) * 2u;
        uint32_t a[4];
        ldm4(a, xs_u32 + a_off * 2u + kb2);
        #pragma unroll
        for (int p = 0; p < 8; p++) {
            uint32_t b[4];
            ldm4(b, wb_cur + (b_off + (uint32_t)(p * 16 * LDK)) * 2u + (uint32_t)(ks * 32));
            mma16(acc[2*p],   a, b[0], b[1]);
            mma16(acc[2*p+1], a, b[2], b[3]);
        }
    }
}

// 8 chunks, 4-stage ring (prefetch depth 3). Chunks 0,1,2 pre-issued into bufs 0,1,2.
__device__ __forceinline__ void gemm_loop(float acc[16][4], const __half* __restrict__ gW,
        uint32_t xs_u32, uint32_t wb_u32, uint32_t a_off, uint32_t b_off, int tid)
{
    for (int kc = 0; kc < 8; kc++) {
        if (kc < 6) CP_WAIT2(); else if (kc == 6) CP_WAIT1(); else CP_WAIT0();
        __syncthreads();                       // chunk kc visible; buf (kc+3)%4 free
        if (kc + 3 < 8)
            issue_chunk(wb_u32 + (uint32_t)((kc + 3) % NSTAGE) * CHUNK_B,
                        gW + (kc + 3) * 32, tid);
        compute_chunk(acc, xs_u32, wb_u32 + (uint32_t)(kc % NSTAGE) * CHUNK_B,
                      kc * 32, a_off, b_off);
    }
}

// ---------------------------------------------------------------------------
// Transpose + fp16 convert: g_Wh[a][d] = W[d][a], g_Uh[o][a] = Uo[a][o]
// ---------------------------------------------------------------------------
__global__ void k_prep(const float* __restrict__ W, const float* __restrict__ Uo)
{
    __shared__ float t[32][33];
    const float* src = blockIdx.z ? Uo : W;
    __half* dst = blockIdx.z ? g_Uh : g_Wh;
    int x0 = blockIdx.x * 32, y0 = blockIdx.y * 32;
    #pragma unroll
    for (int i = 0; i < 32; i += 8)
        t[threadIdx.y + i][threadIdx.x] = src[(y0 + threadIdx.y + i) * 256 + x0 + threadIdx.x];
    __syncthreads();
    #pragma unroll
    for (int i = 0; i < 32; i += 8)
        dst[(x0 + threadIdx.y + i) * 256 + y0 + threadIdx.x] = __float2half_rn(t[threadIdx.x][threadIdx.y + i]);
}

// ---------------------------------------------------------------------------
// Fused kernel: 128-row tile, 512 threads (16 warps), fp16 MMA + ldmatrix.
// Produces betas, g_vu, and flash-style output partials g_part/g_mt.
// ---------------------------------------------------------------------------
__global__ void __launch_bounds__(512, 1)
k_fused(const float* __restrict__ x, const float* __restrict__ mask,
        const float* __restrict__ bvec, const float* __restrict__ u,
        float* __restrict__ betas_out)
{
    extern __shared__ char smc[];
    __half* xs   = (__half*)(smc + O_XS);
    float* bs    = (float*)(smc + O_BS);
    float* us    = (float*)(smc + O_US);
    float* ms    = (float*)(smc + O_MS);
    float* red   = (float*)(smc + O_RED);     // [128][2]
    float* red2  = (float*)(smc + O_RED2);    // [128][2]
    float* vus   = (float*)(smc + O_VUS);     // [128]
    float* mtw   = (float*)(smc + O_MTW);     // [4]
    float* qs    = (float*)(smc + O_QS);      // [128]
    float4* p4   = (float4*)(smc + O_P4);     // [8][64]

    const uint32_t smb    = smem_u32(smc);
    const uint32_t xs_u32 = smb + O_XS;
    const uint32_t wb_u32 = smb + O_WB;

    const int tid  = threadIdx.x;
    const int lane = tid & 31;
    const int wid  = tid >> 5;
    const int wr   = wid >> 1;       // 0..7: 16-row stripe
    const int wc   = wid & 1;        // 0..1: 128-col half
    const int gid  = lane >> 2;
    const int tig  = lane & 3;
    const int row0 = blockIdx.x * TILE_R;

    // ldmatrix per-lane offsets (in halfs)
    const int l7 = lane & 7, l3 = (lane >> 3) & 1, l4 = (lane >> 4) & 1;
    const uint32_t a_off = (uint32_t)((wr*16 + l7 + l3*8) * LDA + l4*8);
    const uint32_t b_off = (uint32_t)((wc*128 + l7 + l4*8) * LDK + l3*8);

    // headers
    if (tid < 256) { bs[tid] = bvec[tid]; us[tid] = u[tid]; }
    if (tid < TILE_R) ms[tid] = mask[row0 + tid];

    // async-prefetch W chunks 0,1,2; then convert x tile to fp16 smem
    issue_chunk(wb_u32, g_Wh, tid);
    issue_chunk(wb_u32 + CHUNK_B, g_Wh + 32, tid);
    issue_chunk(wb_u32 + 2*CHUNK_B, g_Wh + 64, tid);
    {
        const float* xg = x + (size_t)row0 * DD;
        #pragma unroll
        for (int i = 0; i < 16; i++) {
            int idx = tid + i * 512;             // 8192 float4s
            int row = idx >> 6, c4 = (idx & 63) * 4;
            float4 v = *(const float4*)(xg + row * 256 + c4);
            *(__half2*)(xs + row * LDA + c4)     = __floats2half2_rn(v.x, v.y);
            *(__half2*)(xs + row * LDA + c4 + 2) = __floats2half2_rn(v.z, v.w);
        }
    }

    float acc[16][4];

    // ---------------- GEMM1: t = x @ W ----------------
    #pragma unroll
    for (int nt = 0; nt < 16; nt++)
        #pragma unroll
        for (int c = 0; c < 4; c++) acc[nt][c] = 0.0f;

    gemm_loop(acc, g_Wh, xs_u32, wb_u32, a_off, b_off, tid);
    __syncthreads();                 // last-chunk buffer free; xs reads done

    // prefetch Uo chunks 0,1,2 during epilogue1
    issue_chunk(wb_u32, g_Uh, tid);
    issue_chunk(wb_u32 + CHUNK_B, g_Uh + 32, tid);
    issue_chunk(wb_u32 + 2*CHUNK_B, g_Uh + 64, tid);

    // ---------------- epilogue1: bias + normalize + tanh + vu; v -> xs fp16
    // thread rows: r(rh) = wr*16 + rh*8 + gid; cols: wc*128 + nt*8 + 2*tig + (c&1)
    {
        float ss[2] = {0, 0};
        #pragma unroll
        for (int nt = 0; nt < 16; nt++)
            #pragma unroll
            for (int c = 0; c < 4; c++) {
                int col = wc*128 + nt*8 + 2*tig + (c & 1);
                float t = acc[nt][c] + bs[col];
                acc[nt][c] = t;
                ss[c>>1] = fmaf(t, t, ss[c>>1]);
            }
        #pragma unroll
        for (int rh = 0; rh < 2; rh++) {
            ss[rh] += __shfl_xor_sync(0xffffffffu, ss[rh], 1);
            ss[rh] += __shfl_xor_sync(0xffffffffu, ss[rh], 2);
        }
        if (tig == 0) {
            #pragma unroll
            for (int rh = 0; rh < 2; rh++)
                red[(wr*16 + rh*8 + gid)*2 + wc] = ss[rh];
        }
        __syncthreads();
        float invn[2];
        #pragma unroll
        for (int rh = 0; rh < 2; rh++) {
            int r = wr*16 + rh*8 + gid;
            invn[rh] = 1.0f / fmaxf(sqrtf(red[r*2+0] + red[r*2+1]), 1e-12f);
        }
        float vu[2] = {0, 0};
        #pragma unroll
        for (int nt = 0; nt < 16; nt++) {
            #pragma unroll
            for (int c = 0; c < 4; c++) {
                int col = wc*128 + nt*8 + 2*tig + (c & 1);
                float a = acc[nt][c] * invn[c>>1];   // |a| <= 1
                float v = tanh_fast(a);
                acc[nt][c] = v;
                vu[c>>1] = fmaf(v, us[col], vu[c>>1]);
            }
            int cb = wc*128 + nt*8 + 2*tig;
            int r0 = wr*16 + gid;
            *(__half2*)(xs + r0*LDA + cb)     = __floats2half2_rn(acc[nt][0], acc[nt][1]);
            *(__half2*)(xs + (r0+8)*LDA + cb) = __floats2half2_rn(acc[nt][2], acc[nt][3]);
        }
        #pragma unroll
        for (int rh = 0; rh < 2; rh++) {
            vu[rh] += __shfl_xor_sync(0xffffffffu, vu[rh], 1);
            vu[rh] += __shfl_xor_sync(0xffffffffu, vu[rh], 2);
        }
        if (tig == 0) {
            #pragma unroll
            for (int rh = 0; rh < 2; rh++)
                red2[(wr*16 + rh*8 + gid)*2 + wc] = vu[rh];
        }
        __syncthreads();
        if (wc == 0 && tig == 0) {
            #pragma unroll
            for (int rh = 0; rh < 2; rh++) {
                int r = wr*16 + rh*8 + gid;
                float sm = (red2[r*2+0] + red2[r*2+1]) * ms[r];
                g_vu[row0 + r] = sm;
                vus[r] = sm;
            }
        }
    }

    // ---------------- GEMM2: vuo = v @ Uo ----------------
    #pragma unroll
    for (int nt = 0; nt < 16; nt++)
        #pragma unroll
        for (int c = 0; c < 4; c++) acc[nt][c] = 0.0f;

    gemm_loop(acc, g_Uh, xs_u32, wb_u32, a_off, b_off, tid);

    // ---------------- epilogue2: mask + softmax over O -> betas + flash partial
    {
        // tile-local vu max (warps 0-3 reduce vus[128])
        if (wid < 4) {
            float vm = vus[lane + wid*32];
            #pragma unroll
            for (int off = 16; off; off >>= 1) vm = fmaxf(vm, __shfl_xor_sync(0xffffffffu, vm, off));
            if (lane == 0) mtw[wid] = vm;
        }

        float mx[2] = {-3.4e38f, -3.4e38f};
        #pragma unroll
        for (int nt = 0; nt < 16; nt++)
            #pragma unroll
            for (int c = 0; c < 4; c++) {
                int r = wr*16 + ((c>>1)*8) + gid;
                float v = acc[nt][c] * ms[r];
                acc[nt][c] = v;
                mx[c>>1] = fmaxf(mx[c>>1], v);
            }
        #pragma unroll
        for (int rh = 0; rh < 2; rh++) {
            mx[rh] = fmaxf(mx[rh], __shfl_xor_sync(0xffffffffu, mx[rh], 1));
            mx[rh] = fmaxf(mx[rh], __shfl_xor_sync(0xffffffffu, mx[rh], 2));
        }
        __syncthreads();                     // ep1 red/red2 reads done; mtw visible
        const float m_t = fmaxf(fmaxf(mtw[0], mtw[1]), fmaxf(mtw[2], mtw[3]));
        if (tid < TILE_R) qs[tid] = __expf(vus[tid] - m_t) * ms[tid];
        if (tig == 0) {
            #pragma unroll
            for (int rh = 0; rh < 2; rh++)
                red[(wr*16 + rh*8 + gid)*2 + wc] = mx[rh];
        }
        __syncthreads();
        float mxf[2];
        #pragma unroll
        for (int rh = 0; rh < 2; rh++) {
            int r = wr*16 + rh*8 + gid;
            mxf[rh] = fmaxf(red[r*2+0], red[r*2+1]);
        }
        float sume[2] = {0, 0};
        #pragma unroll
        for (int nt = 0; nt < 16; nt++)
            #pragma unroll
            for (int c = 0; c < 4; c++) {
                int r = wr*16 + ((c>>1)*8) + gid;
                float e = __expf(acc[nt][c] - mxf[c>>1]) * ms[r];
                acc[nt][c] = e;
                sume[c>>1] += e;
            }
        #pragma unroll
        for (int rh = 0; rh < 2; rh++) {
            sume[rh] += __shfl_xor_sync(0xffffffffu, sume[rh], 1);
            sume[rh] += __shfl_xor_sync(0xffffffffu, sume[rh], 2);
        }
        if (tig == 0) {
            #pragma unroll
            for (int rh = 0; rh < 2; rh++)
                red2[(wr*16 + rh*8 + gid)*2 + wc] = sume[rh];
        }
        __syncthreads();
        float* bo = betas_out + (size_t)row0 * OO;
        {
            float inv[2];
            #pragma unroll
            for (int rh = 0; rh < 2; rh++) {
                int r = wr*16 + rh*8 + gid;
                float s = red2[r*2+0] + red2[r*2+1];
                inv[rh] = (s == 0.0f) ? 1.0f : __fdividef(1.0f, s);
            }
            int r0 = wr*16 + gid;
            #pragma unroll
            for (int nt = 0; nt < 16; nt++) {
                int cb = wc*128 + nt*8 + 2*tig;
                *(float2*)(bo + (size_t)r0 * OO + cb)     = make_float2(acc[nt][0]*inv[0], acc[nt][1]*inv[0]);
                *(float2*)(bo + (size_t)(r0+8) * OO + cb) = make_float2(acc[nt][2]*inv[1], acc[nt][3]*inv[1]);
            }
        }
        __syncthreads();                     // betas (block-visible) + qs ready

        // ---- in-kernel output partial: P_t[o] = sum_r qs[r]*betas[r][o]*x[r][o]
        {
            const int o4 = (tid & 63) * 4;
            const int rq = tid >> 6;         // 0..7
            float4 pa = make_float4(0.f, 0.f, 0.f, 0.f);
            #pragma unroll 4
            for (int r = rq; r < TILE_R; r += 8) {
                float q = qs[r];
                if (q != 0.0f) {
                    size_t base = ((size_t)(row0 + r)) * OO + o4;
                    float4 xv = *(const float4*)(x + base);
                    float4 bv = *(const float4*)(betas_out + base);
                    pa.x = fmaf(q * xv.x, bv.x, pa.x);
                    pa.y = fmaf(q * xv.y, bv.y, pa.y);
                    pa.z = fmaf(q * xv.z, bv.z, pa.z);
                    pa.w = fmaf(q * xv.w, bv.w, pa.w);
                }
            }
            p4[rq * 64 + (tid & 63)] = pa;
            __syncthreads();
            if (tid < 64) {
                float4 s = p4[tid];
                #pragma unroll
                for (int i = 1; i < 8; i++) {
                    float4 a = p4[i*64 + tid];
                    s.x += a.x; s.y += a.y; s.z += a.z; s.w += a.w;
                }
                *(float4*)&g_part[(size_t)blockIdx.x * OO + tid * 4] = s;
            }
            if (tid == 0) g_mt[blockIdx.x] = m_t;
        }
    }
}

// ---------------------------------------------------------------------------
// Final: alphas = masked softmax of g_vu over S, per batch, then
// out[b][o] = sum_t g_part[t][o] * exp(m_t - M_b) / Z_b   (8 tiles per batch)
// ---------------------------------------------------------------------------
__global__ __launch_bounds__(1024)
void k_final(const float* __restrict__ mask, float* __restrict__ alphas,
             float* __restrict__ out)
{
    __shared__ float redA[32];
    __shared__ float redB[32];
    __shared__ float sc[TPB];
    const int b = blockIdx.x;
    const int s = threadIdx.x;
    const int lane = s & 31, wid = s >> 5;

    float val = g_vu[b*SS + s];
    float m   = mask[b*SS + s];

    float wm = val;
    #pragma unroll
    for (int off = 16; off; off >>= 1) wm = fmaxf(wm, __shfl_xor_sync(0xffffffffu, wm, off));
    if (lane == 0) redA[wid] = wm;
    __syncthreads();
    if (wid == 0) {
        float t = redA[lane];
        #pragma unroll
        for (int off = 16; off; off >>= 1) t = fmaxf(t, __shfl_xor_sync(0xffffffffu, t, off));
        if (lane == 0) redA[0] = t;
    }
    __syncthreads();
    float mx = redA[0];

    float e = __expf(val - mx) * m;
    float wsm = e;
    #pragma unroll
    for (int off = 16; off; off >>= 1) wsm += __shfl_xor_sync(0xffffffffu, wsm, off);
    if (lane == 0) redB[wid] = wsm;
    __syncthreads();
    if (wid == 0) {
        float t = redB[lane];
        #pragma unroll
        for (int off = 16; off; off >>= 1) t += __shfl_xor_sync(0xffffffffu, t, off);
        if (lane == 0) redB[0] = t;
    }
    __syncthreads();
    float sum = redB[0];
    float inv = (sum == 0.0f) ? 1.0f : (1.0f / sum);
    alphas[b*SS + s] = e * inv;

    if (s < TPB) sc[s] = __expf(g_mt[b*TPB + s] - mx) * inv;
    __syncthreads();
    if (s < OO) {
        float acc = 0.0f;
        #pragma unroll
        for (int t = 0; t < TPB; t++)
            acc += g_part[((size_t)(b*TPB + t)) * OO + s] * sc[t];
        out[b*OO + s] = acc;
    }
}

// ---------------------------------------------------------------------------
extern "C" void kernel_launch(void* const* d_in, const int* in_sizes, int n_in,
                              void* d_out, int out_size)
{
    const float* x    = (const float*)d_in[0];   // [B,S,D]
    const float* mask = (const float*)d_in[1];   // [B,S]
    const float* W    = (const float*)d_in[2];   // [D,A]
    const float* bv   = (const float*)d_in[3];   // [A]
    const float* u    = (const float*)d_in[4];   // [A]
    const float* Uo   = (const float*)d_in[5];   // [A,O]

    float* out    = (float*)d_out;               // [B,O]
    float* alphas = out + BB * OO;               // [B,S]
    float* betas  = alphas + BB * SS;            // [B,S,O]

    cudaFuncSetAttribute(k_fused, cudaFuncAttributeMaxDynamicSharedMemorySize, SMEM_BYTES);

    dim3 tg(8, 8, 2), tb(32, 8);
    k_prep<<<tg, tb>>>(W, Uo);
    k_fused<<<NTILE, 512, SMEM_BYTES>>>(x, mask, bv, u, betas);
    k_final<<<BB, 1024>>>(mask, alphas, out);
}